// round 16
// baseline (speedup 1.0000x reference)
#include <cuda_runtime.h>
#include <cuda_bf16.h>
#include <math.h>
#include <stdint.h>

#define NN 50000
#define EE 800000
#define NTIL2 (EE / 64)         // 12500 edge tiles of 64
#define NBLK ((NN + 255) / 256) // 196
#define NPT ((NN + 127) / 128)  // 391 node tiles of 128

typedef unsigned long long u64;
typedef unsigned int u32;

// Scratch (static __device__ — allocation-free per harness rules)
__device__ u32   g_ABh[(size_t)NN * 128];  // A | B per node, bf16x2 packed (64+64 words)
__device__ float g_num[(size_t)NN * 128];  // segment sum accumulator
__device__ float g_t[(size_t)NN * 128];    // node hidden (fp32)
__device__ int   g_deg[NN];
__device__ int   g_cur[NN];                // scatter cursors
__device__ int   g_start[NN];              // run start offsets (sorted order)
__device__ int   g_bsum[256], g_bpre[256]; // scan partials
__device__ u64   g_edges[EE];              // sorted (col<<32 | row)

// silu via hardware tanh: x*sigmoid(x) = h + h*tanh(h), h = x/2
__device__ __forceinline__ float silu_t(float x) {
    float h = 0.5f * x, t;
    asm("tanh.approx.f32 %0, %1;" : "=f"(t) : "f"(h));
    return h + h * t;
}
__device__ __forceinline__ u32 bf2(float lo, float hi) {
    __nv_bfloat162 t = __float22bfloat162_rn(make_float2(lo, hi));
    return *(u32*)&t;
}
__device__ __forceinline__ float2 ubf2(u32 v) {
    return __bfloat1622float2(*(__nv_bfloat162*)&v);
}
__device__ __forceinline__ u32 to_tf32(float x) {
    u32 t; asm("cvt.rna.tf32.f32 %0, %1;" : "=r"(t) : "f"(x)); return t;
}
__device__ __forceinline__ void mma16(float* d, u32 a0, u32 a1, u32 a2, u32 a3,
                                      u32 b0, u32 b1) {
    asm volatile("mma.sync.aligned.m16n8k16.row.col.f32.bf16.bf16.f32 "
        "{%0,%1,%2,%3}, {%4,%5,%6,%7}, {%8,%9}, {%0,%1,%2,%3};"
        : "+f"(d[0]), "+f"(d[1]), "+f"(d[2]), "+f"(d[3])
        : "r"(a0), "r"(a1), "r"(a2), "r"(a3), "r"(b0), "r"(b1));
}
__device__ __forceinline__ void mma8(float* d, u32 a0, u32 a1, u32 a2, u32 a3,
                                     u32 b0, u32 b1) {
    asm volatile("mma.sync.aligned.m16n8k8.row.col.f32.tf32.tf32.f32 "
        "{%0,%1,%2,%3}, {%4,%5,%6,%7}, {%8,%9}, {%0,%1,%2,%3};"
        : "+f"(d[0]), "+f"(d[1]), "+f"(d[2]), "+f"(d[3])
        : "r"(a0), "r"(a1), "r"(a2), "r"(a3), "r"(b0), "r"(b1));
}
__device__ __forceinline__ void red4(float* p, float a, float b, float c, float d) {
    asm volatile("red.global.add.v4.f32 [%0], {%1, %2, %3, %4};"
                 :: "l"(p), "f"(a), "f"(b), "f"(c), "f"(d) : "memory");
}

__global__ void k_zero() {
    int i = blockIdx.x * blockDim.x + threadIdx.x;
    int stride = gridDim.x * blockDim.x;
    float4 z = make_float4(0.f, 0.f, 0.f, 0.f);
    for (int j = i; j < NN * 128 / 4; j += stride) ((float4*)g_num)[j] = z;
    for (int j = i; j < NN; j += stride) g_deg[j] = 0;
}

__global__ void k_deg(const int* __restrict__ ei) {
    int i = blockIdx.x * blockDim.x + threadIdx.x;
    int stride = gridDim.x * blockDim.x;
    for (int e = i; e < EE; e += stride) atomicAdd(&g_deg[ei[e]], 1);
}

// -------- counting-sort scan + scatter --------
__global__ void k_bsum() {
    __shared__ int s[256];
    int b = blockIdx.x, tid = threadIdx.x, i = b * 256 + tid;
    s[tid] = (i < NN) ? g_deg[i] : 0;
    __syncthreads();
    for (int off = 128; off; off >>= 1) {
        if (tid < off) s[tid] += s[tid + off];
        __syncthreads();
    }
    if (!tid) g_bsum[b] = s[0];
}
__global__ void k_sscan() {
    __shared__ int s[256];
    int tid = threadIdx.x;
    int v0 = (tid < NBLK) ? g_bsum[tid] : 0;
    s[tid] = v0;
    __syncthreads();
    for (int off = 1; off < 256; off <<= 1) {
        int v = (tid >= off) ? s[tid - off] : 0;
        __syncthreads();
        s[tid] += v;
        __syncthreads();
    }
    if (tid < NBLK) g_bpre[tid] = s[tid] - v0;
}
__global__ void k_wcur() {
    __shared__ int s[256];
    int b = blockIdx.x, tid = threadIdx.x, i = b * 256 + tid;
    int d = (i < NN) ? g_deg[i] : 0;
    s[tid] = d;
    __syncthreads();
    for (int off = 1; off < 256; off <<= 1) {
        int v = (tid >= off) ? s[tid - off] : 0;
        __syncthreads();
        s[tid] += v;
        __syncthreads();
    }
    if (i < NN) {
        int st = s[tid] - d + g_bpre[b];
        g_cur[i] = st;
        g_start[i] = st;
    }
}
__global__ void k_scatter(const int* __restrict__ ei) {
    int i = blockIdx.x * blockDim.x + threadIdx.x;
    int stride = gridDim.x * blockDim.x;
    for (int e = i; e < EE; e += stride) {
        int r = ei[e], c = ei[EE + e];
        int pos = atomicAdd(&g_cur[r], 1);
        g_edges[pos] = ((u64)(u32)c << 32) | (u32)r;
    }
}

// ===================== tf32 MMA fabric (verified R6/R9/R10) =====================
// As: [128 r][128 c] tf32, swizzle c' = c ^ ((r&7)<<2).
// B table: [128 k][128 n_phys] tf32, swizzle np ^ ((k&3)<<3), column permutation
// nlog = ((nb>>1)<<4)+((c>>1)<<2)+((nb&1)<<1)+(c&1).

__device__ __forceinline__ void build_btab(u32* Bs, const float* W, int k0, int ldw, int tid) {
    for (int idx = tid; idx < 16384; idx += 512) {
        int k = idx >> 7, np = idx & 127;
        int nb = np >> 3, c = np & 7;
        int nlog = ((nb >> 1) << 4) + ((c >> 1) << 2) + ((nb & 1) << 1) + (c & 1);
        Bs[k * 128 + (np ^ ((k & 3) << 3))] = to_tf32(W[(k0 + k) * ldw + nlog]);
    }
}

__device__ __forceinline__ void mma_pass(const u32* As, const u32* Bs,
                                         float acc[2][4][4], int arow, int warp_n,
                                         int q, int a8) {
    #pragma unroll
    for (int ks = 0; ks < 16; ks++) {
        int kk = ks * 8 + q;
        int swn = (kk & 3) << 3;
        u32 bf0[4], bf1[4];
        #pragma unroll
        for (int nb = 0; nb < 4; nb++) {
            int np = ((warp_n * 4 + nb) << 3) + a8;
            bf0[nb] = Bs[kk * 128 + (np ^ swn)];
            bf1[nb] = Bs[(kk + 4) * 128 + (np ^ ((kk + 4) & 3) * 8)];
        }
        #pragma unroll
        for (int mt = 0; mt < 2; mt++) {
            int rr = arow + mt * 16 + a8;
            int ca = kk ^ ((rr & 7) << 2);
            u32 a0 = As[rr * 128 + ca];
            u32 a2 = As[rr * 128 + (ca ^ 4)];
            u32 a1 = As[(rr + 8) * 128 + ca];
            u32 a3 = As[(rr + 8) * 128 + (ca ^ 4)];
            #pragma unroll
            for (int nb = 0; nb < 4; nb++)
                mma8(acc[mt][nb], a0, a1, a2, a3, bf0[nb], bf1[nb]);
        }
    }
}

__device__ __forceinline__ void fill_as(u32* As, const float4* src, int r, int kq,
                                        float scale) {
    int sw = (r & 7) << 2;
    #pragma unroll
    for (int i4 = 0; i4 < 8; i4++) {
        float4 v = src[i4];
        int c0 = kq * 32 + i4 * 4;
        uint4 o;
        o.x = to_tf32(v.x * scale); o.y = to_tf32(v.y * scale);
        o.z = to_tf32(v.z * scale); o.w = to_tf32(v.w * scale);
        *(uint4*)(As + r * 128 + (c0 ^ sw)) = o;
    }
}

// ---------------- K1: g_ABh = bf16(h @ [We1_top | We1_bot]) (tf32 MMA) -------------
__global__ void __launch_bounds__(512, 1) k_pre_mma(const float* __restrict__ h,
                                                    const float* __restrict__ We1) {
    extern __shared__ u32 smu[];
    u32* As  = smu;           // 16384 words
    u32* Bs0 = smu + 16384;
    u32* Bs1 = smu + 32768;
    int tid = threadIdx.x, wid = tid >> 5, lane = tid & 31;
    int warp_m = wid >> 2, warp_n = wid & 3;
    int q = lane & 3, a8 = lane >> 2;
    build_btab(Bs0, We1, 0, 128, tid);
    build_btab(Bs1, We1, 128, 128, tid);
    int r = tid >> 2, kq = tid & 3;
    int arow = warp_m * 32;
    for (int tile = blockIdx.x; tile < NPT; tile += gridDim.x) {
        __syncthreads();
        int node = min(tile * 128 + r, NN - 1);
        fill_as(As, (const float4*)(h + (size_t)node * 128 + kq * 32), r, kq, 1.0f);
        __syncthreads();
        #pragma unroll
        for (int half = 0; half < 2; half++) {
            float acc[2][4][4] = {};
            mma_pass(As, half ? Bs1 : Bs0, acc, arow, warp_n, q, a8);
            #pragma unroll
            for (int mt = 0; mt < 2; mt++) {
                int row0 = tile * 128 + arow + mt * 16 + a8;
                #pragma unroll
                for (int p = 0; p < 2; p++) {
                    int c = warp_n * 32 + p * 16 + q * 4;
                    int nA = 2 * p, nB = 2 * p + 1;
                    if (row0 < NN) {
                        uint2 o = make_uint2(bf2(acc[mt][nA][0], acc[mt][nA][1]),
                                             bf2(acc[mt][nB][0], acc[mt][nB][1]));
                        *(uint2*)(g_ABh + (size_t)row0 * 128 + half * 64 + (c >> 1)) = o;
                    }
                    if (row0 + 8 < NN) {
                        uint2 o = make_uint2(bf2(acc[mt][nA][2], acc[mt][nA][3]),
                                             bf2(acc[mt][nB][2], acc[mt][nB][3]));
                        *(uint2*)(g_ABh + (size_t)(row0 + 8) * 128 + half * 64 + (c >> 1)) = o;
                    }
                }
            }
        }
    }
}

// ---------------- K2: edge kernel, M=64, 2 CTAs/SM, A-run dedup ----------------
// smem: Bs 32KB, As 16KB, sA (A-row cache) 16KB, Cs 33KB = 97KB.
__global__ void __launch_bounds__(256, 2) k_edge5(
        const float* __restrict__ xz,
        const float* __restrict__ We1, const float* __restrict__ be1,
        const float* __restrict__ We2, const float* __restrict__ be2) {
    extern __shared__ u32 smu[];
    u32* Bs = smu;                       // 8192
    u32* As = smu + 8192;                // 4096
    u32* sA = smu + 12288;               // 4096 (64 rows x 64 words A cache)
    float* Cs = (float*)(smu + 16384);   // 64*132 floats
    __shared__ int s_row[64];
    __shared__ float sW1l[128], sB1[128];

    int tid = threadIdx.x, wid = tid >> 5, lane = tid & 31;
    int warp_m = wid >> 2, warp_n = wid & 3;
    int q = lane & 3, a8 = lane >> 2;

    // edge bf16 B table (unpermuted — Cs staging handles layout)
    for (int idx = tid; idx < 8192; idx += 256) {
        int n = idx >> 6, w = idx & 63;
        Bs[n * 64 + (w ^ ((n & 7) << 2))] =
            bf2(We2[(2 * w) * 128 + n], We2[(2 * w + 1) * 128 + n]);
    }
    if (tid < 128) { sW1l[tid] = We1[256 * 128 + tid]; sB1[tid] = be1[tid]; }

    int r = tid >> 2, kq = tid & 3;
    float4 be2v = *(const float4*)(be2 + lane * 4);

    for (int tile = blockIdx.x; tile < NTIL2; tile += gridDim.x) {
        int base = tile << 6;
        __syncthreads();   // prev Cs/s_row/sA consumed
        // ---- phase 1: edge decode, dist, A-run-leader load into sA ----
        u64 pr = g_edges[base + r];
        int nr = (int)(u32)pr, nc = (int)(u32)(pr >> 32);
        if (kq == 0) s_row[r] = nr;
        int ls = max(g_start[nr] - base, 0);   // run start within tile (sorted)
        float x0 = xz[nr * 3 + 0], y0 = xz[nr * 3 + 1], z0 = xz[nr * 3 + 2];
        float x1 = xz[nc * 3 + 0], y1 = xz[nc * 3 + 1], z1 = xz[nc * 3 + 2];
        float dx = x0 - x1, dy = y0 - y1, dz = z0 - z1;
        float u = (dx * dx + dy * dy + dz * dz) / (2.f * z0 * z1);
        float dist = acoshf(1.f + u);
        if (r == ls) {
            const uint4* ga = (const uint4*)(g_ABh + (size_t)nr * 128 + kq * 16);
            uint4* da = (uint4*)(sA + r * 64 + kq * 16);
            da[0] = ga[0]; da[1] = ga[1]; da[2] = ga[2]; da[3] = ga[3];
        }
        __syncthreads();
        // ---- phase 2: pre = silu(A+B+dist*w1l+b1) -> bf16 As ----
        {
            const uint4* pa = (const uint4*)(sA + ls * 64 + kq * 16);
            const uint4* pb = (const uint4*)(g_ABh + (size_t)nc * 128 + 64 + kq * 16);
            int sw = (r & 7) << 2;
            #pragma unroll
            for (int j = 0; j < 4; j++) {
                uint4 a4 = pa[j], b4 = pb[j];
                int c0 = kq * 32 + 8 * j;
                float2 a0 = ubf2(a4.x), a1 = ubf2(a4.y), a2 = ubf2(a4.z), a3 = ubf2(a4.w);
                float2 b0 = ubf2(b4.x), b1 = ubf2(b4.y), b2 = ubf2(b4.z), b3 = ubf2(b4.w);
                float4 w0 = *(const float4*)(sW1l + c0);
                float4 w1 = *(const float4*)(sW1l + c0 + 4);
                float4 e0 = *(const float4*)(sB1 + c0);
                float4 e1 = *(const float4*)(sB1 + c0 + 4);
                uint4 o;
                o.x = bf2(silu_t(a0.x + b0.x + dist * w0.x + e0.x),
                          silu_t(a0.y + b0.y + dist * w0.y + e0.y));
                o.y = bf2(silu_t(a1.x + b1.x + dist * w0.z + e0.z),
                          silu_t(a1.y + b1.y + dist * w0.w + e0.w));
                o.z = bf2(silu_t(a2.x + b2.x + dist * w1.x + e1.x),
                          silu_t(a2.y + b2.y + dist * w1.y + e1.y));
                o.w = bf2(silu_t(a3.x + b3.x + dist * w1.z + e1.z),
                          silu_t(a3.y + b3.y + dist * w1.w + e1.w));
                *(uint4*)(As + r * 64 + ((kq * 16 + 4 * j) ^ sw)) = o;
            }
        }
        __syncthreads();

        // ---- MMA: warp (warp_m, warp_n) -> rows warp_m*32+, cols warp_n*32+ ----
        float acc[2][4][4];
        #pragma unroll
        for (int mt = 0; mt < 2; mt++)
            #pragma unroll
            for (int nb = 0; nb < 4; nb++)
                #pragma unroll
                for (int x = 0; x < 4; x++) acc[mt][nb][x] = 0.f;

        int arow = warp_m * 32;
        #pragma unroll
        for (int ks = 0; ks < 8; ks++) {
            u32 bf0[4], bf1[4];
            #pragma unroll
            for (int nb = 0; nb < 4; nb++) {
                int n = warp_n * 32 + nb * 8 + a8;
                int sw = (n & 7) << 2;
                bf0[nb] = Bs[n * 64 + ((ks * 8 + q) ^ sw)];
                bf1[nb] = Bs[n * 64 + ((ks * 8 + q + 4) ^ sw)];
            }
            #pragma unroll
            for (int mt = 0; mt < 2; mt++) {
                int r0 = arow + mt * 16 + a8;
                int sw = (r0 & 7) << 2;
                u32 a0 = As[r0 * 64 + ((ks * 8 + q) ^ sw)];
                u32 a1 = As[(r0 + 8) * 64 + ((ks * 8 + q) ^ sw)];
                u32 a2 = As[r0 * 64 + ((ks * 8 + q + 4) ^ sw)];
                u32 a3 = As[(r0 + 8) * 64 + ((ks * 8 + q + 4) ^ sw)];
                #pragma unroll
                for (int nb = 0; nb < 4; nb++)
                    mma16(acc[mt][nb], a0, a1, a2, a3, bf0[nb], bf1[nb]);
            }
        }

        // ---- stage C fragments to Cs (stride 132) ----
        #pragma unroll
        for (int mt = 0; mt < 2; mt++) {
            int r0 = arow + mt * 16 + a8;
            #pragma unroll
            for (int nb = 0; nb < 4; nb++) {
                int c = warp_n * 32 + nb * 8 + 2 * q;
                *(float2*)(Cs + r0 * 132 + c) = make_float2(acc[mt][nb][0], acc[mt][nb][1]);
                *(float2*)(Cs + (r0 + 8) * 132 + c) = make_float2(acc[mt][nb][2], acc[mt][nb][3]);
            }
        }
        __syncthreads();

        // ---- segmented reduction: warp = rows [wid*8, +8), lane = col quad ----
        {
            int rb = wid * 8;
            int cur = s_row[rb];
            float4 sum;
            {
                float4 c = *(const float4*)(Cs + rb * 132 + lane * 4);
                sum.x = silu_t(c.x + be2v.x); sum.y = silu_t(c.y + be2v.y);
                sum.z = silu_t(c.z + be2v.z); sum.w = silu_t(c.w + be2v.w);
            }
            #pragma unroll
            for (int i = 1; i < 8; i++) {
                int rr = rb + i;
                int dest = s_row[rr];
                float4 c = *(const float4*)(Cs + rr * 132 + lane * 4);
                float4 v;
                v.x = silu_t(c.x + be2v.x); v.y = silu_t(c.y + be2v.y);
                v.z = silu_t(c.z + be2v.z); v.w = silu_t(c.w + be2v.w);
                if (dest != cur) {
                    red4(g_num + (size_t)cur * 128 + lane * 4, sum.x, sum.y, sum.z, sum.w);
                    sum = v; cur = dest;
                } else {
                    sum.x += v.x; sum.y += v.y; sum.z += v.z; sum.w += v.w;
                }
            }
            red4(g_num + (size_t)cur * 128 + lane * 4, sum.x, sum.y, sum.z, sum.w);
        }
    }
}

// ---------------- K3a: t = silu([h, agg] @ Wn1 + bn1) (tf32 MMA, split-K) ---------
__global__ void __launch_bounds__(512, 1) k_node1_mma(const float* __restrict__ h,
        const float* __restrict__ Wn1, const float* __restrict__ bn1) {
    extern __shared__ u32 smu[];
    u32* As  = smu;
    u32* Bs0 = smu + 16384;
    u32* Bs1 = smu + 32768;
    int tid = threadIdx.x, wid = tid >> 5, lane = tid & 31;
    int warp_m = wid >> 2, warp_n = wid & 3;
    int q = lane & 3, a8 = lane >> 2;
    build_btab(Bs0, Wn1, 0, 128, tid);
    build_btab(Bs1, Wn1, 128, 128, tid);
    int r = tid >> 2, kq = tid & 3;
    int arow = warp_m * 32;
    float4 bv[2];
    bv[0] = *(const float4*)(bn1 + warp_n * 32 + q * 4);
    bv[1] = *(const float4*)(bn1 + warp_n * 32 + 16 + q * 4);
    for (int tile = blockIdx.x; tile < NPT; tile += gridDim.x) {
        __syncthreads();
        int node = min(tile * 128 + r, NN - 1);
        fill_as(As, (const float4*)(h + (size_t)node * 128 + kq * 32), r, kq, 1.0f);
        __syncthreads();
        float acc[2][4][4] = {};
        mma_pass(As, Bs0, acc, arow, warp_n, q, a8);
        __syncthreads();
        float scale = 1.0f / fmaxf((float)g_deg[node], 1.0f);
        fill_as(As, (const float4*)(g_num + (size_t)node * 128 + kq * 32), r, kq, scale);
        __syncthreads();
        mma_pass(As, Bs1, acc, arow, warp_n, q, a8);
        #pragma unroll
        for (int mt = 0; mt < 2; mt++) {
            int row0 = tile * 128 + arow + mt * 16 + a8;
            #pragma unroll
            for (int p = 0; p < 2; p++) {
                int c = warp_n * 32 + p * 16 + q * 4;
                int nA = 2 * p, nB = 2 * p + 1;
                if (row0 < NN)
                    *(float4*)(g_t + (size_t)row0 * 128 + c) =
                        make_float4(silu_t(acc[mt][nA][0] + bv[p].x),
                                    silu_t(acc[mt][nA][1] + bv[p].y),
                                    silu_t(acc[mt][nB][0] + bv[p].z),
                                    silu_t(acc[mt][nB][1] + bv[p].w));
                if (row0 + 8 < NN)
                    *(float4*)(g_t + (size_t)(row0 + 8) * 128 + c) =
                        make_float4(silu_t(acc[mt][nA][2] + bv[p].x),
                                    silu_t(acc[mt][nA][3] + bv[p].y),
                                    silu_t(acc[mt][nB][2] + bv[p].z),
                                    silu_t(acc[mt][nB][3] + bv[p].w));
            }
        }
    }
}

// ---------------- K3b: out = h + t @ Wn2 + bn2 (tf32 MMA) -----------------
__global__ void __launch_bounds__(512, 1) k_node2_mma(const float* __restrict__ h,
        const float* __restrict__ Wn2, const float* __restrict__ bn2,
        float* __restrict__ out) {
    extern __shared__ u32 smu[];
    u32* As = smu;
    u32* Bs = smu + 16384;
    int tid = threadIdx.x, wid = tid >> 5, lane = tid & 31;
    int warp_m = wid >> 2, warp_n = wid & 3;
    int q = lane & 3, a8 = lane >> 2;
    build_btab(Bs, Wn2, 0, 128, tid);
    int r = tid >> 2, kq = tid & 3;
    int arow = warp_m * 32;
    float4 bv[2];
    bv[0] = *(const float4*)(bn2 + warp_n * 32 + q * 4);
    bv[1] = *(const float4*)(bn2 + warp_n * 32 + 16 + q * 4);
    for (int tile = blockIdx.x; tile < NPT; tile += gridDim.x) {
        __syncthreads();
        int node = min(tile * 128 + r, NN - 1);
        fill_as(As, (const float4*)(g_t + (size_t)node * 128 + kq * 32), r, kq, 1.0f);
        __syncthreads();
        float acc[2][4][4] = {};
        mma_pass(As, Bs, acc, arow, warp_n, q, a8);
        #pragma unroll
        for (int mt = 0; mt < 2; mt++) {
            int row0 = tile * 128 + arow + mt * 16 + a8;
            #pragma unroll
            for (int p = 0; p < 2; p++) {
                int c = warp_n * 32 + p * 16 + q * 4;
                int nA = 2 * p, nB = 2 * p + 1;
                if (row0 < NN) {
                    float4 hv = *(const float4*)(h + (size_t)row0 * 128 + c);
                    *(float4*)(out + (size_t)row0 * 128 + c) =
                        make_float4(hv.x + acc[mt][nA][0] + bv[p].x,
                                    hv.y + acc[mt][nA][1] + bv[p].y,
                                    hv.z + acc[mt][nB][0] + bv[p].z,
                                    hv.w + acc[mt][nB][1] + bv[p].w);
                }
                if (row0 + 8 < NN) {
                    float4 hv = *(const float4*)(h + (size_t)(row0 + 8) * 128 + c);
                    *(float4*)(out + (size_t)(row0 + 8) * 128 + c) =
                        make_float4(hv.x + acc[mt][nA][2] + bv[p].x,
                                    hv.y + acc[mt][nA][3] + bv[p].y,
                                    hv.z + acc[mt][nB][2] + bv[p].z,
                                    hv.w + acc[mt][nB][3] + bv[p].w);
                }
            }
        }
    }
}

extern "C" void kernel_launch(void* const* d_in, const int* in_sizes, int n_in,
                              void* d_out, int out_size) {
    (void)in_sizes; (void)n_in; (void)out_size;
    const float* xz  = (const float*)d_in[0];
    const float* h   = (const float*)d_in[1];
    const float* We1 = (const float*)d_in[2];
    const float* be1 = (const float*)d_in[3];
    const float* We2 = (const float*)d_in[4];
    const float* be2 = (const float*)d_in[5];
    const float* Wn1 = (const float*)d_in[6];
    const float* bn1 = (const float*)d_in[7];
    const float* Wn2 = (const float*)d_in[8];
    const float* bn2 = (const float*)d_in[9];
    const int*   ei  = (const int*)d_in[10];
    float* out = (float*)d_out;

    cudaFuncSetAttribute(k_pre_mma,   cudaFuncAttributeMaxDynamicSharedMemorySize, 196608);
    cudaFuncSetAttribute(k_edge5,     cudaFuncAttributeMaxDynamicSharedMemorySize, 99328);
    cudaFuncSetAttribute(k_node1_mma, cudaFuncAttributeMaxDynamicSharedMemorySize, 196608);
    cudaFuncSetAttribute(k_node2_mma, cudaFuncAttributeMaxDynamicSharedMemorySize, 131072);

    k_zero<<<1024, 256>>>();
    k_deg<<<1024, 256>>>(ei);
    k_bsum<<<NBLK, 256>>>();
    k_sscan<<<1, 256>>>();
    k_wcur<<<NBLK, 256>>>();
    k_scatter<<<1024, 256>>>(ei);
    k_pre_mma<<<152, 512, 196608>>>(h, We1);
    k_edge5<<<304, 256, 99328>>>(xz, We1, be1, We2, be2);
    k_node1_mma<<<152, 512, 196608>>>(h, Wn1, bn1);
    k_node2_mma<<<152, 512, 131072>>>(h, Wn2, bn2, out);
}